// round 15
// baseline (speedup 1.0000x reference)
#include <cuda_runtime.h>
#include <cuda_fp16.h>
#include <math.h>
#include <stdint.h>

#define D        128
#define N_NODES  5000
#define WINDOW   10
#define N_TOTAL  50000
#define NE       131072
#define HID      1024
#define TEDGE    45000
#define TE2      90000

// ---------------- device scratch ----------------
__device__ __align__(16) float g_h[N_TOTAL * D];
__device__ int   g_cnt[N_TOTAL];
__device__ int   g_csr[N_TOTAL + 1];
__device__ int   g_cur[N_TOTAL];
__device__ int   g_nidx[NE];
__device__ int   g_midx[NE];
__device__ __align__(16) float g_x2[N_NODES * 512];
__device__ __align__(16) float g_zero1024[1024];

// fp16 intermediates
__device__ __align__(16) __half g_P16[(size_t)N_TOTAL * HID];
__device__ __align__(16) __half g_Q16[(size_t)N_TOTAL * HID];
__device__ __align__(16) __half g_m16[(size_t)NE * D];
__device__ __align__(16) __half g_zr16[(size_t)N_TOTAL * 256];   // xz+hz | xr+hr
__device__ __align__(16) __half g_xhh16[(size_t)N_TOTAL * 256];  // xh | hh
__device__ __align__(16) __half g_hid[(size_t)N_NODES * HID];

// transposed fp16 weights, layout [N][K]
__device__ __align__(16) __half g_W1t[HID * 256];
__device__ __align__(16) __half g_W2t[D * HID];
__device__ __align__(16) __half g_Gzr_i[256 * 256], g_Gxh_i[256 * 256];
__device__ __align__(16) __half g_Gzr_t[256 * 256], g_Gxh_t[256 * 256];
__device__ __align__(16) float  g_bzr_i[256], g_bxh_i[256], g_bzr_t[256], g_bxh_t[256];
__device__ __align__(16) __half g_R1t[HID * D];
__device__ __align__(16) __half g_R2t[512 * HID];

// ---------------- helpers ----------------
__device__ __forceinline__ uint32_t smem_u32(const void* p) {
    uint32_t a;
    asm("{ .reg .u64 t; cvta.to.shared.u64 t, %1; cvt.u32.u64 %0, t; }" : "=r"(a) : "l"(p));
    return a;
}
__device__ __forceinline__ void ldsm4(uint32_t& r0, uint32_t& r1, uint32_t& r2, uint32_t& r3, uint32_t addr) {
    asm volatile("ldmatrix.sync.aligned.m8n8.x4.shared.b16 {%0,%1,%2,%3}, [%4];"
                 : "=r"(r0), "=r"(r1), "=r"(r2), "=r"(r3) : "r"(addr));
}
__device__ __forceinline__ void mma16816(float* c, const uint32_t* a, const uint32_t* b) {
    asm volatile("mma.sync.aligned.m16n8k16.row.col.f32.f16.f16.f32 "
                 "{%0,%1,%2,%3}, {%4,%5,%6,%7}, {%8,%9}, {%0,%1,%2,%3};"
                 : "+f"(c[0]), "+f"(c[1]), "+f"(c[2]), "+f"(c[3])
                 : "r"(a[0]), "r"(a[1]), "r"(a[2]), "r"(a[3]), "r"(b[0]), "r"(b[1]));
}
__device__ __forceinline__ void cp16(uint32_t saddr, const void* g) {
    asm volatile("cp.async.cg.shared.global [%0], [%1], 16;" :: "r"(saddr), "l"(g));
}
#define CP_COMMIT() asm volatile("cp.async.commit_group;" ::: "memory")
#define CP_WAIT0()  asm volatile("cp.async.wait_group 0;" ::: "memory")

__device__ __forceinline__ uint32_t pack_h2(float x, float y) {
    __half2 h = __floats2half2_rn(x, y);
    return *(uint32_t*)&h;
}
__device__ __forceinline__ uint32_t hadd2_relu(uint32_t a, uint32_t b) {
    __half2 s = __hadd2(*(__half2*)&a, *(__half2*)&b);
    __half2 z = __float2half2_rn(0.f);
    __half2 r = __hmax2(s, z);
    return *(uint32_t*)&r;
}
__device__ __forceinline__ uint32_t havg2(uint32_t a, uint32_t b) {
    __half2 s = __hadd2(*(__half2*)&a, *(__half2*)&b);
    __half2 hlf = __float2half2_rn(0.5f);
    __half2 r = __hmul2(s, hlf);
    return *(uint32_t*)&r;
}

// ---------------- fp16 HMMA GEMM, double-buffered, 2 CTAs/SM ----------------
// AMODE 0:  A fp32 row-major stride lda
// AMODE 3:  A fp16 row-major stride lda (cp.async)
// AMODE 4:  A[r,k] = relu(P16[nidx[r]][k] + Q16[midx[r]][k])      (bases hoisted)
// AMODE 5:  same with analytic temporal indices                   (bases hoisted)
// AMODE 12: dual P|Q: fp32 Af loader both z; z selects B/bias/output
// AMODE 13: dual GRU (interaction): A = [CSR-mean(m16) | fp32 h], K=256; z selects B/bias/out
// AMODE 14: dual GRU (temporal):    A = [temporal-mean(m16) | fp32 h], K=256
#define ASTR   56
#define PANEL  (128 * ASTR)
#define PANELB (PANEL * 2)               // 14336 B
#define BUF_BYTES (2 * PANELB)           // 28672 (A, B)
#define SMEM_BYTES (2 * BUF_BYTES)       // 57344

template<int AMODE, int OUTSPLIT, int RELU>
__global__ __launch_bounds__(256, 2)
void hmma_gemm(const float* __restrict__ Af,
               const __half* __restrict__ Ph,
               const __half* __restrict__ Qh,
               const __half* __restrict__ Ah_g,
               int lda,
               const int* __restrict__ idxA, const int* __restrict__ idxB,
               const int* __restrict__ csr,
               const __half* __restrict__ Bw,
               const __half* __restrict__ Bw2,
               int ldb,
               const float* __restrict__ bias,
               const float* __restrict__ bias2,
               float* __restrict__ Cf,
               __half* __restrict__ Chi,
               __half* __restrict__ Chi2,
               int ldc, int M, int K)
{
    extern __shared__ __half smbuf[];
    const uint32_t sbase = smem_u32(smbuf);

    const int t = threadIdx.x, lane = t & 31, w = t >> 5;
    const int wm = w >> 2, wn = w & 3;
    const int m0 = blockIdx.y * 128, n0 = blockIdx.x * 128;
    const bool DUAL = (AMODE == 12 || AMODE == 13 || AMODE == 14);
    const int z1 = DUAL ? (int)blockIdx.z : 0;
    const int lrow = t >> 1, lhalf = t & 1;
    const uint32_t arow_off = ((uint32_t)(lrow * ASTR + lhalf * 16)) << 1;

    const __half* Bsel = z1 ? Bw2 : Bw;
    const float*  bsel = z1 ? bias2 : bias;
    __half*       Csel = z1 ? Chi2 : Chi;

    // hoisted loader state
    const __half *gP = nullptr, *gQ = nullptr;       // AMODE 4/5
    const __half *tA = nullptr, *tB = nullptr;       // AMODE 14
    int segBeg = 0, segEnd = 0;                      // AMODE 13
    {
        int gRow = m0 + lrow; if (gRow >= M) gRow = M - 1;
        if (AMODE == 4 || AMODE == 5) {
            int n_, m_;
            if (AMODE == 4) { n_ = idxA[gRow]; m_ = idxB[gRow]; }
            else {
                if (gRow < TEDGE) { n_ = gRow;                   m_ = gRow + N_NODES; }
                else              { n_ = gRow - TEDGE + N_NODES; m_ = gRow - TEDGE;   }
            }
            gP = Ph + (size_t)n_ * HID;
            gQ = Qh + (size_t)m_ * HID;
        } else if (AMODE == 13) {
            segBeg = csr[gRow]; segEnd = csr[gRow + 1];
        } else if (AMODE == 14) {
            const int v = gRow;
            if (v >= N_NODES) tA = Ah_g + (size_t)(v - N_NODES) * D;
            if (v < TEDGE)    tB = Ah_g + (size_t)(TEDGE + v) * D;
        }
    }

    float acc[4][4][4];
#pragma unroll
    for (int i = 0; i < 4; ++i)
#pragma unroll
        for (int j = 0; j < 4; ++j)
#pragma unroll
            for (int q = 0; q < 4; ++q) acc[i][j][q] = 0.f;

    uint32_t rh[8];

    auto loadFp32 = [&](const float* src) {
        float vv[16];
#pragma unroll
        for (int i = 0; i < 16; i += 4) {
            float4 v = *(const float4*)(src + i);
            vv[i] = v.x; vv[i+1] = v.y; vv[i+2] = v.z; vv[i+3] = v.w;
        }
#pragma unroll
        for (int i = 0; i < 8; ++i) rh[i] = pack_h2(vv[2*i], vv[2*i+1]);
    };

    auto loadA = [&](int s) {
        if (AMODE == 3) return;
        const int k0 = s << 5;
        int gRow = m0 + lrow; if (gRow >= M) gRow = M - 1;
        const int koff = k0 + lhalf * 16;
        if (AMODE == 4 || AMODE == 5) {
            const uint4* p = (const uint4*)(gP + koff);
            const uint4* q = (const uint4*)(gQ + koff);
            uint4 p0 = p[0], p1 = p[1], q0 = q[0], q1 = q[1];
            rh[0] = hadd2_relu(p0.x, q0.x); rh[1] = hadd2_relu(p0.y, q0.y);
            rh[2] = hadd2_relu(p0.z, q0.z); rh[3] = hadd2_relu(p0.w, q0.w);
            rh[4] = hadd2_relu(p1.x, q1.x); rh[5] = hadd2_relu(p1.y, q1.y);
            rh[6] = hadd2_relu(p1.z, q1.z); rh[7] = hadd2_relu(p1.w, q1.w);
        } else if (AMODE == 13) {
            if (k0 < 128) {     // CSR-mean of m16
                float sx[16];
#pragma unroll
                for (int i = 0; i < 16; ++i) sx[i] = 0.f;
                for (int j = segBeg; j < segEnd; ++j) {
                    const uint4* r = (const uint4*)(Ah_g + (size_t)j * D + koff);
                    uint4 v0 = r[0], v1 = r[1];
                    uint32_t ww[8] = {v0.x, v0.y, v0.z, v0.w, v1.x, v1.y, v1.z, v1.w};
#pragma unroll
                    for (int i = 0; i < 8; ++i) {
                        float2 f = __half22float2(*(__half2*)&ww[i]);
                        sx[2*i]     += f.x;
                        sx[2*i + 1] += f.y;
                    }
                }
                const float scale = (segEnd > segBeg) ? 1.f / (float)(segEnd - segBeg) : 0.f;
#pragma unroll
                for (int i = 0; i < 8; ++i)
                    rh[i] = pack_h2(sx[2*i] * scale, sx[2*i+1] * scale);
            } else {            // fp32 h at column koff-128
                loadFp32(Af + (size_t)gRow * D + (koff - 128));
            }
        } else if (AMODE == 14) {
            if (k0 < 128) {     // temporal mean of m16
                uint4 a0 = make_uint4(0,0,0,0), a1 = a0, b0 = a0, b1 = a0;
                if (tA) { const uint4* r = (const uint4*)(tA + koff); a0 = r[0]; a1 = r[1]; }
                if (tB) { const uint4* r = (const uint4*)(tB + koff); b0 = r[0]; b1 = r[1]; }
                if (tA && tB) {
                    rh[0] = havg2(a0.x, b0.x); rh[1] = havg2(a0.y, b0.y);
                    rh[2] = havg2(a0.z, b0.z); rh[3] = havg2(a0.w, b0.w);
                    rh[4] = havg2(a1.x, b1.x); rh[5] = havg2(a1.y, b1.y);
                    rh[6] = havg2(a1.z, b1.z); rh[7] = havg2(a1.w, b1.w);
                } else if (tA) {
                    rh[0] = a0.x; rh[1] = a0.y; rh[2] = a0.z; rh[3] = a0.w;
                    rh[4] = a1.x; rh[5] = a1.y; rh[6] = a1.z; rh[7] = a1.w;
                } else {
                    rh[0] = b0.x; rh[1] = b0.y; rh[2] = b0.z; rh[3] = b0.w;
                    rh[4] = b1.x; rh[5] = b1.y; rh[6] = b1.z; rh[7] = b1.w;
                }
            } else {
                loadFp32(Af + (size_t)gRow * D + (koff - 128));
            }
        } else {   // AMODE 0, AMODE 12 (both z): fp32 source Af
            loadFp32(Af + (size_t)gRow * lda + koff);
        }
    };
    auto stsA = [&](int buf) {
        if (AMODE == 3) return;
        __half* dh = smbuf + (size_t)buf * (BUF_BYTES / 2) + lrow * ASTR + lhalf * 16;
        *(uint4*)dh       = make_uint4(rh[0], rh[1], rh[2], rh[3]);
        *(uint4*)(dh + 8) = make_uint4(rh[4], rh[5], rh[6], rh[7]);
    };
    auto cpaA = [&](int s, int buf) {   // AMODE 3
        const int k0 = s << 5;
        int gRow = m0 + lrow; if (gRow >= M) gRow = M - 1;
        const size_t off = (size_t)gRow * lda + k0 + lhalf * 16;
        const uint32_t d = sbase + buf * BUF_BYTES + arow_off;
        cp16(d,      Ah_g + off);
        cp16(d + 16, Ah_g + off + 8);
    };
    auto cpaB = [&](int s, int buf) {
        const int k0 = s << 5;
        const size_t off = (size_t)(n0 + lrow) * ldb + k0 + lhalf * 16;
        const uint32_t d = sbase + buf * BUF_BYTES + PANELB + arow_off;
        cp16(d,      Bsel + off);
        cp16(d + 16, Bsel + off + 8);
    };
    auto domma = [&](int buf) {
        const uint32_t bb = sbase + buf * BUF_BYTES;
#pragma unroll
        for (int kk = 0; kk < 2; ++kk) {
            const int kc = kk * 16;
            uint32_t bh[4][2];
#pragma unroll
            for (int p = 0; p < 2; ++p) {
                const uint32_t boff =
                    ((uint32_t)((wn * 32 + p * 16 + ((lane >> 4) << 3) + (lane & 7)) * ASTR
                                + kc + (((lane >> 3) & 1) << 3))) << 1;
                uint32_t r0, r1, r2, r3;
                ldsm4(r0, r1, r2, r3, bb + PANELB + boff);
                bh[p * 2][0] = r0; bh[p * 2][1] = r1; bh[p * 2 + 1][0] = r2; bh[p * 2 + 1][1] = r3;
            }
#pragma unroll
            for (int mt = 0; mt < 4; ++mt) {
                const uint32_t aoff =
                    ((uint32_t)((wm * 64 + mt * 16 + (lane & 15)) * ASTR + kc + ((lane >> 4) << 3))) << 1;
                uint32_t ah[4];
                ldsm4(ah[0], ah[1], ah[2], ah[3], bb + aoff);
#pragma unroll
                for (int nt = 0; nt < 4; ++nt)
                    mma16816(acc[mt][nt], ah, bh[nt]);
            }
        }
    };

    const int steps = K >> 5;
    if (AMODE == 3) cpaA(0, 0); else loadA(0);
    cpaB(0, 0);
    CP_COMMIT();
    if (AMODE != 3) stsA(0);
    CP_WAIT0();
    __syncthreads();

    for (int s = 0; s < steps; ++s) {
        const int buf = s & 1, nbuf = buf ^ 1;
        const bool more = (s + 1 < steps);
        if (more) {
            if (AMODE == 3) cpaA(s + 1, nbuf); else loadA(s + 1);
            cpaB(s + 1, nbuf);
            CP_COMMIT();
        }
        domma(buf);
        if (more) {
            if (AMODE != 3) stsA(nbuf);
            CP_WAIT0();
            __syncthreads();
        }
    }

    // ---- epilogue ----
    const int r0base = m0 + wm * 64 + (lane >> 2);
    const int cbase  = n0 + wn * 32 + (lane & 3) * 2;
#pragma unroll
    for (int mt = 0; mt < 4; ++mt) {
#pragma unroll
        for (int nt = 0; nt < 4; ++nt) {
            const int cB = cbase + nt * 8;
            const float b0v = bsel[cB], b1v = bsel[cB + 1];
            float c0 = acc[mt][nt][0] + b0v, c1 = acc[mt][nt][1] + b1v;
            float c2 = acc[mt][nt][2] + b0v, c3 = acc[mt][nt][3] + b1v;
            if (RELU) {
                c0 = fmaxf(c0, 0.f); c1 = fmaxf(c1, 0.f);
                c2 = fmaxf(c2, 0.f); c3 = fmaxf(c3, 0.f);
            }
            const int gR0 = r0base + mt * 16, gR1 = gR0 + 8;
            if (OUTSPLIT == 0) {
                if (gR0 < M) *(float2*)(Cf + (size_t)gR0 * ldc + cB) = make_float2(c0, c1);
                if (gR1 < M) *(float2*)(Cf + (size_t)gR1 * ldc + cB) = make_float2(c2, c3);
            } else {
                if (gR0 < M) *(uint32_t*)(Csel + (size_t)gR0 * ldc + cB) = pack_h2(c0, c1);
                if (gR1 < M) *(uint32_t*)(Csel + (size_t)gR1 * ldc + cB) = pack_h2(c2, c3);
            }
        }
    }
}

// ---------------- fused weight prep ----------------
#define S_W1 262144
#define S_W2 131072
#define S_GN 65536
#define S_R1 131072
#define S_R2 524288
#define S_BIAS 1024
#define S_TOTAL (S_W1 + S_W2 + 4*S_GN + S_R1 + S_R2 + S_BIAS)

__global__ void cvt_all_kernel(const float* __restrict__ W1, const float* __restrict__ W2,
                               const float* __restrict__ GiW, const float* __restrict__ GiU,
                               const float* __restrict__ GtW, const float* __restrict__ GtU,
                               const float* __restrict__ R1, const float* __restrict__ R2,
                               const float* __restrict__ gib, const float* __restrict__ gtb)
{
    int i = blockIdx.x * blockDim.x + threadIdx.x;
    if (i >= S_TOTAL) return;
    if (i < S_W1) {
        int k = i / 1024, n = i % 1024;
        g_W1t[(size_t)n * 256 + k] = __float2half_rn(W1[i]);
        return;
    }
    i -= S_W1;
    if (i < S_W2) {
        int k = i / 128, n = i % 128;
        g_W2t[(size_t)n * 1024 + k] = __float2half_rn(W2[i]);
        return;
    }
    i -= S_W2;
    if (i < 4 * S_GN) {
        int seg = i / S_GN, j = i % S_GN;
        int n = j / 256, k = j % 256;
        const float* Wm = (seg < 2) ? GiW : GtW;
        const float* Um = (seg < 2) ? GiU : GtU;
        __half* dst = (seg == 0) ? g_Gzr_i : (seg == 1) ? g_Gxh_i : (seg == 2) ? g_Gzr_t : g_Gxh_t;
        float v;
        if ((seg & 1) == 0) {      // zr-sum weights: [W_zr ; U_zr]
            v = (k < 128) ? Wm[k * 384 + n] : Um[(k - 128) * 384 + n];
        } else {                   // xh|hh block-diagonal
            if (n < 128) v = (k < 128) ? Wm[k * 384 + 256 + n] : 0.f;
            else         v = (k >= 128) ? Um[(k - 128) * 384 + 256 + (n - 128)] : 0.f;
        }
        dst[(size_t)n * 256 + k] = __float2half_rn(v);
        return;
    }
    i -= 4 * S_GN;
    if (i < S_R1) {
        int k = i / 1024, n = i % 1024;
        g_R1t[(size_t)n * 128 + k] = __float2half_rn(R1[i]);
        return;
    }
    i -= S_R1;
    if (i < S_R2) {
        int k = i / 512, n = i % 512;
        g_R2t[(size_t)n * 1024 + k] = __float2half_rn(R2[i]);
        return;
    }
    i -= S_R2;
    {   // biases: 4 groups of 256
        int grp = i / 256, c = i % 256;
        if (grp == 0) g_bzr_i[c] = gib[c] + gib[384 + c];
        else if (grp == 1) g_bxh_i[c] = (c < 128) ? gib[256 + c] : gib[640 + (c - 128)];
        else if (grp == 2) g_bzr_t[c] = gtb[c] + gtb[384 + c];
        else g_bxh_t[c] = (c < 128) ? gtb[256 + c] : gtb[640 + (c - 128)];
    }
}

// ---------------- glue ----------------
__global__ void init_h_kernel(const int* __restrict__ nodes, const float* __restrict__ embed)
{
    int i = blockIdx.x * blockDim.x + threadIdx.x;
    if (i >= N_TOTAL * D) return;
    int row = i >> 7, c = i & 127;
    g_h[i] = embed[nodes[row / WINDOW] * D + c];
}
__global__ void zero_cnt_kernel()
{
    int i = blockIdx.x * blockDim.x + threadIdx.x;
    if (i < N_TOTAL) g_cnt[i] = 0;
}
__global__ void count_ie_kernel(const int* __restrict__ ie)
{
    int e = blockIdx.x * blockDim.x + threadIdx.x;
    if (e >= NE) return;
    int tt = ie[e * 3 + 0] % WINDOW, d2 = ie[e * 3 + 2];
    atomicAdd(&g_cnt[tt * N_NODES + d2], 1);
}
__global__ void scan_kernel()
{
    __shared__ int ssum[1024];
    const int tid = threadIdx.x;
    const int CH = (N_TOTAL + 1023) / 1024;
    const int base = tid * CH;
    int s = 0;
    for (int i = 0; i < CH; ++i) {
        int idx = base + i;
        if (idx < N_TOTAL) s += g_cnt[idx];
    }
    ssum[tid] = s;
    __syncthreads();
    for (int off = 1; off < 1024; off <<= 1) {
        int v = (tid >= off) ? ssum[tid - off] : 0;
        __syncthreads();
        ssum[tid] += v;
        __syncthreads();
    }
    int run = ssum[tid] - s;
    for (int i = 0; i < CH; ++i) {
        int idx = base + i;
        if (idx < N_TOTAL) {
            g_csr[idx] = run;
            g_cur[idx] = run;
            run += g_cnt[idx];
        }
    }
    if (tid == 1023) g_csr[N_TOTAL] = run;
}
__global__ void place_kernel(const int* __restrict__ ie)
{
    int e = blockIdx.x * blockDim.x + threadIdx.x;
    if (e >= NE) return;
    int tt = ie[e * 3 + 0] % WINDOW, s = ie[e * 3 + 1], d2 = ie[e * 3 + 2];
    int dst = tt * N_NODES + d2;
    int pos = atomicAdd(&g_cur[dst], 1);
    g_nidx[pos] = tt * N_NODES + s;
    g_midx[pos] = dst;
}
__device__ __forceinline__ float sigmoidf(float x) { return 1.f / (1.f + expf(-x)); }
__global__ void gru_kernel()
{
    int i = blockIdx.x * blockDim.x + threadIdx.x;
    if (i >= N_TOTAL * 64) return;
    int r = i >> 6, c2 = i & 63;
    const __half2* zr = (const __half2*)(g_zr16 + (size_t)r * 256);
    const __half2* xh = (const __half2*)(g_xhh16 + (size_t)r * 256);
    float2 zz = __half22float2(zr[c2]);
    float2 rr = __half22float2(zr[64 + c2]);
    float2 xv = __half22float2(xh[c2]);
    float2 hv = __half22float2(xh[64 + c2]);
    float2 h = *(float2*)(g_h + (size_t)r * 128 + c2 * 2);
    float z0 = sigmoidf(zz.x), z1 = sigmoidf(zz.y);
    float r0 = sigmoidf(rr.x), r1 = sigmoidf(rr.y);
    float hc0 = tanhf(xv.x + r0 * hv.x), hc1 = tanhf(xv.y + r1 * hv.y);
    float2 o;
    o.x = z0 * h.x + (1.f - z0) * hc0;
    o.y = z1 * h.y + (1.f - z1) * hc1;
    *(float2*)(g_h + (size_t)r * 128 + c2 * 2) = o;
}
__global__ void logits_softmax_kernel(const float* __restrict__ W3,
                                      const float* __restrict__ b3,
                                      float* __restrict__ out)
{
    const int row = blockIdx.x;
    const int w = threadIdx.x >> 5, lane = threadIdx.x & 31;
    __shared__ float lg[10];
    float s = 0.f;
    for (int k = lane; k < 512; k += 32)
        s += g_x2[(size_t)row * 512 + k] * W3[k * 10 + w];
#pragma unroll
    for (int o = 16; o; o >>= 1) s += __shfl_down_sync(0xffffffff, s, o);
    if (lane == 0) lg[w] = s + b3[w];
    __syncthreads();
    if (threadIdx.x == 0) {
        float mx = lg[0];
#pragma unroll
        for (int c = 1; c < 10; ++c) mx = fmaxf(mx, lg[c]);
        float e[10], sum = 0.f;
#pragma unroll
        for (int c = 0; c < 10; ++c) { e[c] = expf(lg[c] - mx); sum += e[c]; }
#pragma unroll
        for (int c = 0; c < 10; ++c) out[row * 10 + c] = e[c] / sum;
    }
}

// ---------------- host ----------------
extern "C" void kernel_launch(void* const* d_in, const int* in_sizes, int n_in,
                              void* d_out, int out_size)
{
    const int*   ie        = (const int*)  d_in[0];
    const int*   nodes     = (const int*)  d_in[1];
    const float* embed     = (const float*)d_in[2];
    const float* msg_W1    = (const float*)d_in[3];
    const float* msg_b1    = (const float*)d_in[4];
    const float* msg_W2    = (const float*)d_in[5];
    const float* msg_b2    = (const float*)d_in[6];
    const float* gru_int_W = (const float*)d_in[7];
    const float* gru_int_U = (const float*)d_in[8];
    const float* gru_int_b = (const float*)d_in[9];
    const float* gru_tmp_W = (const float*)d_in[10];
    const float* gru_tmp_U = (const float*)d_in[11];
    const float* gru_tmp_b = (const float*)d_in[12];
    const float* ro_W1     = (const float*)d_in[13];
    const float* ro_b1     = (const float*)d_in[14];
    const float* ro_W2     = (const float*)d_in[15];
    const float* ro_b2     = (const float*)d_in[16];
    const float* ro_W3     = (const float*)d_in[17];
    const float* ro_b3     = (const float*)d_in[18];
    float* out = (float*)d_out;

    float *h_p, *x2_p, *zero_p;
    float *bzri_p, *bxhi_p, *bzrt_p, *bxht_p;
    int *nidx_p, *midx_p, *csr_p;
    __half *P_p, *Q_p, *m_p, *zr_p, *xhh_p, *hid_p;
    __half *w1, *w2, *gzri, *gxhi, *gzrt, *gxht, *r1, *r2;
    cudaGetSymbolAddress((void**)&h_p, g_h);
    cudaGetSymbolAddress((void**)&x2_p, g_x2);
    cudaGetSymbolAddress((void**)&zero_p, g_zero1024);
    cudaGetSymbolAddress((void**)&nidx_p, g_nidx);
    cudaGetSymbolAddress((void**)&midx_p, g_midx);
    cudaGetSymbolAddress((void**)&csr_p, g_csr);
    cudaGetSymbolAddress((void**)&P_p, g_P16);
    cudaGetSymbolAddress((void**)&Q_p, g_Q16);
    cudaGetSymbolAddress((void**)&m_p, g_m16);
    cudaGetSymbolAddress((void**)&zr_p, g_zr16);
    cudaGetSymbolAddress((void**)&xhh_p, g_xhh16);
    cudaGetSymbolAddress((void**)&hid_p, g_hid);
    cudaGetSymbolAddress((void**)&w1, g_W1t);
    cudaGetSymbolAddress((void**)&w2, g_W2t);
    cudaGetSymbolAddress((void**)&gzri, g_Gzr_i);
    cudaGetSymbolAddress((void**)&gxhi, g_Gxh_i);
    cudaGetSymbolAddress((void**)&gzrt, g_Gzr_t);
    cudaGetSymbolAddress((void**)&gxht, g_Gxh_t);
    cudaGetSymbolAddress((void**)&bzri_p, g_bzr_i);
    cudaGetSymbolAddress((void**)&bxhi_p, g_bxh_i);
    cudaGetSymbolAddress((void**)&bzrt_p, g_bzr_t);
    cudaGetSymbolAddress((void**)&bxht_p, g_bxh_t);
    cudaGetSymbolAddress((void**)&r1, g_R1t);
    cudaGetSymbolAddress((void**)&r2, g_R2t);

    cudaFuncSetAttribute(hmma_gemm<0,1,1>,  cudaFuncAttributeMaxDynamicSharedMemorySize, SMEM_BYTES);
    cudaFuncSetAttribute(hmma_gemm<3,0,1>,  cudaFuncAttributeMaxDynamicSharedMemorySize, SMEM_BYTES);
    cudaFuncSetAttribute(hmma_gemm<4,1,1>,  cudaFuncAttributeMaxDynamicSharedMemorySize, SMEM_BYTES);
    cudaFuncSetAttribute(hmma_gemm<5,1,1>,  cudaFuncAttributeMaxDynamicSharedMemorySize, SMEM_BYTES);
    cudaFuncSetAttribute(hmma_gemm<12,1,0>, cudaFuncAttributeMaxDynamicSharedMemorySize, SMEM_BYTES);
    cudaFuncSetAttribute(hmma_gemm<13,1,0>, cudaFuncAttributeMaxDynamicSharedMemorySize, SMEM_BYTES);
    cudaFuncSetAttribute(hmma_gemm<14,1,0>, cudaFuncAttributeMaxDynamicSharedMemorySize, SMEM_BYTES);

    const int EL = 256;
    cvt_all_kernel<<<(S_TOTAL + EL-1)/EL, EL>>>(msg_W1, msg_W2, gru_int_W, gru_int_U,
                                                gru_tmp_W, gru_tmp_U, ro_W1, ro_W2,
                                                gru_int_b, gru_tmp_b);
    init_h_kernel<<<(N_TOTAL*D + EL-1)/EL, EL>>>(nodes, embed);
    zero_cnt_kernel<<<(N_TOTAL + EL-1)/EL, EL>>>();
    count_ie_kernel<<<(NE + EL-1)/EL, EL>>>(ie);
    scan_kernel<<<1, 1024>>>();
    place_kernel<<<(NE + EL-1)/EL, EL>>>(ie);

    const int MT_E = NE / 128;
    const int MT_T = (TE2 + 127) / 128;
    const int MT_N = (N_TOTAL + 127) / 128;
    const int MT_R = (N_NODES + 127) / 128;

    for (int it = 0; it < 2; ++it) {
        // ---- interaction stage ----
        hmma_gemm<12,1,0><<<dim3(8, MT_N, 2), 256, SMEM_BYTES>>>(
            h_p, nullptr, nullptr, nullptr, D, nullptr, nullptr, nullptr,
            w1, w1 + 128, 256, msg_b1, zero_p, nullptr, P_p, Q_p, HID, N_TOTAL, D);
        hmma_gemm<4,1,1><<<dim3(1, MT_E), 256, SMEM_BYTES>>>(
            nullptr, P_p, Q_p, nullptr, 0, nidx_p, midx_p, nullptr,
            w2, nullptr, HID, msg_b2, nullptr, nullptr, m_p, nullptr, D, NE, HID);
        hmma_gemm<13,1,0><<<dim3(2, MT_N, 2), 256, SMEM_BYTES>>>(
            h_p, nullptr, nullptr, m_p, D, nullptr, nullptr, csr_p,
            gzri, gxhi, 256, bzri_p, bxhi_p, nullptr, zr_p, xhh_p, 256, N_TOTAL, 256);
        gru_kernel<<<(N_TOTAL*64 + EL-1)/EL, EL>>>();

        // ---- temporal stage ----
        hmma_gemm<12,1,0><<<dim3(8, MT_N, 2), 256, SMEM_BYTES>>>(
            h_p, nullptr, nullptr, nullptr, D, nullptr, nullptr, nullptr,
            w1, w1 + 128, 256, msg_b1, zero_p, nullptr, P_p, Q_p, HID, N_TOTAL, D);
        hmma_gemm<5,1,1><<<dim3(1, MT_T), 256, SMEM_BYTES>>>(
            nullptr, P_p, Q_p, nullptr, 0, nullptr, nullptr, nullptr,
            w2, nullptr, HID, msg_b2, nullptr, nullptr, m_p, nullptr, D, TE2, HID);
        hmma_gemm<14,1,0><<<dim3(2, MT_N, 2), 256, SMEM_BYTES>>>(
            h_p, nullptr, nullptr, m_p, D, nullptr, nullptr, nullptr,
            gzrt, gxht, 256, bzrt_p, bxht_p, nullptr, zr_p, xhh_p, 256, N_TOTAL, 256);
        gru_kernel<<<(N_TOTAL*64 + EL-1)/EL, EL>>>();
    }

    // ---- readout ----
    hmma_gemm<0,1,1><<<dim3(8, MT_R), 256, SMEM_BYTES>>>(
        h_p, nullptr, nullptr, nullptr, D, nullptr, nullptr, nullptr,
        r1, nullptr, D, ro_b1, nullptr, nullptr, hid_p, nullptr, HID, N_NODES, D);
    hmma_gemm<3,0,1><<<dim3(4, MT_R), 256, SMEM_BYTES>>>(
        nullptr, nullptr, nullptr, hid_p, HID, nullptr, nullptr, nullptr,
        r2, nullptr, HID, ro_b2, nullptr, x2_p, nullptr, nullptr, 512, N_NODES, HID);
    logits_softmax_kernel<<<N_NODES, 320>>>(ro_W3, ro_b3, out);
}

// round 16
// speedup vs baseline: 1.1053x; 1.1053x over previous
#include <cuda_runtime.h>
#include <cuda_fp16.h>
#include <math.h>
#include <stdint.h>

#define D        128
#define N_NODES  5000
#define WINDOW   10
#define N_TOTAL  50000
#define NE       131072
#define HID      1024
#define TEDGE    45000
#define TE2      90000

// ---------------- device scratch ----------------
__device__ __align__(16) float g_h[N_TOTAL * D];
__device__ __align__(16) __half g_h16[N_TOTAL * D];   // fp16 mirror of g_h
__device__ int   g_cnt[N_TOTAL];
__device__ int   g_csr[N_TOTAL + 1];
__device__ int   g_cur[N_TOTAL];
__device__ int   g_nidx[NE];
__device__ int   g_midx[NE];
__device__ __align__(16) float g_x2[N_NODES * 512];
__device__ __align__(16) float g_zero1024[1024];

// fp16 intermediates
__device__ __align__(16) __half g_P16[(size_t)N_TOTAL * HID];
__device__ __align__(16) __half g_Q16[(size_t)N_TOTAL * HID];
__device__ __align__(16) __half g_m16[(size_t)NE * D];
__device__ __align__(16) __half g_xg16[(size_t)N_TOTAL * 384];
__device__ __align__(16) __half g_hg16[(size_t)N_TOTAL * 384];
__device__ __align__(16) __half g_hid[(size_t)N_NODES * HID];

// transposed fp16 weights, layout [N][K]
__device__ __align__(16) __half g_W1t[HID * 256];
__device__ __align__(16) __half g_W2t[D * HID];
__device__ __align__(16) __half g_GiW[384 * D];
__device__ __align__(16) __half g_GiU[384 * D];
__device__ __align__(16) __half g_GtW[384 * D];
__device__ __align__(16) __half g_GtU[384 * D];
__device__ __align__(16) __half g_R1t[HID * D];
__device__ __align__(16) __half g_R2t[512 * HID];

// ---------------- helpers ----------------
__device__ __forceinline__ uint32_t smem_u32(const void* p) {
    uint32_t a;
    asm("{ .reg .u64 t; cvta.to.shared.u64 t, %1; cvt.u32.u64 %0, t; }" : "=r"(a) : "l"(p));
    return a;
}
__device__ __forceinline__ void ldsm4(uint32_t& r0, uint32_t& r1, uint32_t& r2, uint32_t& r3, uint32_t addr) {
    asm volatile("ldmatrix.sync.aligned.m8n8.x4.shared.b16 {%0,%1,%2,%3}, [%4];"
                 : "=r"(r0), "=r"(r1), "=r"(r2), "=r"(r3) : "r"(addr));
}
__device__ __forceinline__ void mma16816(float* c, const uint32_t* a, const uint32_t* b) {
    asm volatile("mma.sync.aligned.m16n8k16.row.col.f32.f16.f16.f32 "
                 "{%0,%1,%2,%3}, {%4,%5,%6,%7}, {%8,%9}, {%0,%1,%2,%3};"
                 : "+f"(c[0]), "+f"(c[1]), "+f"(c[2]), "+f"(c[3])
                 : "r"(a[0]), "r"(a[1]), "r"(a[2]), "r"(a[3]), "r"(b[0]), "r"(b[1]));
}
__device__ __forceinline__ void cp16(uint32_t saddr, const void* g) {
    asm volatile("cp.async.cg.shared.global [%0], [%1], 16;" :: "r"(saddr), "l"(g));
}
#define CP_COMMIT() asm volatile("cp.async.commit_group;" ::: "memory")
#define CP_WAIT0()  asm volatile("cp.async.wait_group 0;" ::: "memory")

__device__ __forceinline__ uint32_t pack_h2(float x, float y) {
    __half2 h = __floats2half2_rn(x, y);
    return *(uint32_t*)&h;
}
__device__ __forceinline__ uint32_t hadd2_relu(uint32_t a, uint32_t b) {
    __half2 s = __hadd2(*(__half2*)&a, *(__half2*)&b);
    __half2 z = __float2half2_rn(0.f);
    __half2 r = __hmax2(s, z);
    return *(uint32_t*)&r;
}
__device__ __forceinline__ uint32_t havg2(uint32_t a, uint32_t b) {
    __half2 s = __hadd2(*(__half2*)&a, *(__half2*)&b);
    __half2 hlf = __float2half2_rn(0.5f);
    __half2 r = __hmul2(s, hlf);
    return *(uint32_t*)&r;
}

// ---------------- fp16 HMMA GEMM, double-buffered, 2 CTAs/SM ----------------
// AMODE 0:  A fp32 row-major stride lda
// AMODE 3:  A fp16 row-major stride lda (cp.async)
// AMODE 4:  A[r,k] = relu(P16[nidx[r]][k] + Q16[midx[r]][k])      (bases hoisted)
// AMODE 5:  same with analytic temporal indices                   (bases hoisted)
// AMODE 8:  dual interaction-GRU: z=0 CSR-mean(m16 via Ah_g); z=1 fp16 h via Ph
// AMODE 9:  dual temporal-GRU:    z=0 temporal-mean(m16);     z=1 fp16 h via Ph
// AMODE 12: dual P|Q: fp16 h loader via Ph, both z; z selects B/bias/output
#define ASTR   56
#define PANEL  (128 * ASTR)
#define PANELB (PANEL * 2)               // 14336 B
#define BUF_BYTES (2 * PANELB)           // 28672 (A, B)
#define SMEM_BYTES (2 * BUF_BYTES)       // 57344

template<int AMODE, int OUTSPLIT, int RELU>
__global__ __launch_bounds__(256, 2)
void hmma_gemm(const float* __restrict__ Af,
               const __half* __restrict__ Ph,
               const __half* __restrict__ Qh,
               const __half* __restrict__ Ah_g,
               int lda,
               const int* __restrict__ idxA, const int* __restrict__ idxB,
               const int* __restrict__ csr,
               const __half* __restrict__ Bw,
               const __half* __restrict__ Bw2,
               int ldb,
               const float* __restrict__ bias,
               const float* __restrict__ bias2,
               float* __restrict__ Cf,
               __half* __restrict__ Chi,
               __half* __restrict__ Chi2,
               int ldc, int M, int K)
{
    extern __shared__ __half smbuf[];
    const uint32_t sbase = smem_u32(smbuf);

    const int t = threadIdx.x, lane = t & 31, w = t >> 5;
    const int wm = w >> 2, wn = w & 3;
    const int m0 = blockIdx.y * 128, n0 = blockIdx.x * 128;
    const bool DUAL = (AMODE == 8 || AMODE == 9 || AMODE == 12);
    const int z1 = DUAL ? (int)blockIdx.z : 0;
    const int lrow = t >> 1, lhalf = t & 1;
    const uint32_t arow_off = ((uint32_t)(lrow * ASTR + lhalf * 16)) << 1;

    const __half* Bsel = z1 ? Bw2 : Bw;
    const float*  bsel = z1 ? bias2 : bias;
    __half*       Csel = z1 ? Chi2 : Chi;

    // hoisted loader state
    const __half *gP = nullptr, *gQ = nullptr;       // AMODE 4/5
    const __half *tA = nullptr, *tB = nullptr;       // AMODE 9 z=0
    int segBeg = 0, segEnd = 0;                      // AMODE 8 z=0
    {
        int gRow = m0 + lrow; if (gRow >= M) gRow = M - 1;
        if (AMODE == 4 || AMODE == 5) {
            int n_, m_;
            if (AMODE == 4) { n_ = idxA[gRow]; m_ = idxB[gRow]; }
            else {
                if (gRow < TEDGE) { n_ = gRow;                   m_ = gRow + N_NODES; }
                else              { n_ = gRow - TEDGE + N_NODES; m_ = gRow - TEDGE;   }
            }
            gP = Ph + (size_t)n_ * HID;
            gQ = Qh + (size_t)m_ * HID;
        } else if (AMODE == 8 && z1 == 0) {
            segBeg = csr[gRow]; segEnd = csr[gRow + 1];
        } else if (AMODE == 9 && z1 == 0) {
            const int v = gRow;
            if (v >= N_NODES) tA = Ah_g + (size_t)(v - N_NODES) * D;
            if (v < TEDGE)    tB = Ah_g + (size_t)(TEDGE + v) * D;
        }
    }

    float acc[4][4][4];
#pragma unroll
    for (int i = 0; i < 4; ++i)
#pragma unroll
        for (int j = 0; j < 4; ++j)
#pragma unroll
            for (int q = 0; q < 4; ++q) acc[i][j][q] = 0.f;

    uint32_t rh[8];

    auto loadH16 = [&](const __half* src) {
        uint4 a0 = ((const uint4*)src)[0];
        uint4 a1 = ((const uint4*)src)[1];
        rh[0] = a0.x; rh[1] = a0.y; rh[2] = a0.z; rh[3] = a0.w;
        rh[4] = a1.x; rh[5] = a1.y; rh[6] = a1.z; rh[7] = a1.w;
    };

    auto loadA = [&](int s) {
        if (AMODE == 3) return;
        const int k0 = s << 5;
        int gRow = m0 + lrow; if (gRow >= M) gRow = M - 1;
        const int koff = k0 + lhalf * 16;
        if (AMODE == 4 || AMODE == 5) {
            const uint4* p = (const uint4*)(gP + koff);
            const uint4* q = (const uint4*)(gQ + koff);
            uint4 p0 = p[0], p1 = p[1], q0 = q[0], q1 = q[1];
            rh[0] = hadd2_relu(p0.x, q0.x); rh[1] = hadd2_relu(p0.y, q0.y);
            rh[2] = hadd2_relu(p0.z, q0.z); rh[3] = hadd2_relu(p0.w, q0.w);
            rh[4] = hadd2_relu(p1.x, q1.x); rh[5] = hadd2_relu(p1.y, q1.y);
            rh[6] = hadd2_relu(p1.z, q1.z); rh[7] = hadd2_relu(p1.w, q1.w);
        } else if (AMODE == 9 && z1 == 0) {
            uint4 a0 = make_uint4(0,0,0,0), a1 = a0, b0 = a0, b1 = a0;
            if (tA) { const uint4* r = (const uint4*)(tA + koff); a0 = r[0]; a1 = r[1]; }
            if (tB) { const uint4* r = (const uint4*)(tB + koff); b0 = r[0]; b1 = r[1]; }
            if (tA && tB) {
                rh[0] = havg2(a0.x, b0.x); rh[1] = havg2(a0.y, b0.y);
                rh[2] = havg2(a0.z, b0.z); rh[3] = havg2(a0.w, b0.w);
                rh[4] = havg2(a1.x, b1.x); rh[5] = havg2(a1.y, b1.y);
                rh[6] = havg2(a1.z, b1.z); rh[7] = havg2(a1.w, b1.w);
            } else if (tA) {
                rh[0] = a0.x; rh[1] = a0.y; rh[2] = a0.z; rh[3] = a0.w;
                rh[4] = a1.x; rh[5] = a1.y; rh[6] = a1.z; rh[7] = a1.w;
            } else {
                rh[0] = b0.x; rh[1] = b0.y; rh[2] = b0.z; rh[3] = b0.w;
                rh[4] = b1.x; rh[5] = b1.y; rh[6] = b1.z; rh[7] = b1.w;
            }
        } else if (AMODE == 8 && z1 == 0) {
            float sx[16];
#pragma unroll
            for (int i = 0; i < 16; ++i) sx[i] = 0.f;
            for (int j = segBeg; j < segEnd; ++j) {
                const uint4* r = (const uint4*)(Ah_g + (size_t)j * D + koff);
                uint4 v0 = r[0], v1 = r[1];
                uint32_t ww[8] = {v0.x, v0.y, v0.z, v0.w, v1.x, v1.y, v1.z, v1.w};
#pragma unroll
                for (int i = 0; i < 8; ++i) {
                    float2 f = __half22float2(*(__half2*)&ww[i]);
                    sx[2*i]     += f.x;
                    sx[2*i + 1] += f.y;
                }
            }
            const float scale = (segEnd > segBeg) ? 1.f / (float)(segEnd - segBeg) : 0.f;
#pragma unroll
            for (int i = 0; i < 8; ++i)
                rh[i] = pack_h2(sx[2*i] * scale, sx[2*i+1] * scale);
        } else if (AMODE == 12 || ((AMODE == 8 || AMODE == 9) && z1 == 1)) {
            // fp16 h mirror via Ph, row stride D
            loadH16(Ph + (size_t)gRow * D + koff);
        } else {   // AMODE 0: fp32 source Af
            const float* src = Af + (size_t)gRow * lda + koff;
            float vv[16];
#pragma unroll
            for (int i = 0; i < 16; i += 4) {
                float4 v = *(const float4*)(src + i);
                vv[i] = v.x; vv[i+1] = v.y; vv[i+2] = v.z; vv[i+3] = v.w;
            }
#pragma unroll
            for (int i = 0; i < 8; ++i) rh[i] = pack_h2(vv[2*i], vv[2*i+1]);
        }
    };
    auto stsA = [&](int buf) {
        if (AMODE == 3) return;
        __half* dh = smbuf + (size_t)buf * (BUF_BYTES / 2) + lrow * ASTR + lhalf * 16;
        *(uint4*)dh       = make_uint4(rh[0], rh[1], rh[2], rh[3]);
        *(uint4*)(dh + 8) = make_uint4(rh[4], rh[5], rh[6], rh[7]);
    };
    auto cpaA = [&](int s, int buf) {   // AMODE 3
        const int k0 = s << 5;
        int gRow = m0 + lrow; if (gRow >= M) gRow = M - 1;
        const size_t off = (size_t)gRow * lda + k0 + lhalf * 16;
        const uint32_t d = sbase + buf * BUF_BYTES + arow_off;
        cp16(d,      Ah_g + off);
        cp16(d + 16, Ah_g + off + 8);
    };
    auto cpaB = [&](int s, int buf) {
        const int k0 = s << 5;
        const size_t off = (size_t)(n0 + lrow) * ldb + k0 + lhalf * 16;
        const uint32_t d = sbase + buf * BUF_BYTES + PANELB + arow_off;
        cp16(d,      Bsel + off);
        cp16(d + 16, Bsel + off + 8);
    };
    auto domma = [&](int buf) {
        const uint32_t bb = sbase + buf * BUF_BYTES;
#pragma unroll
        for (int kk = 0; kk < 2; ++kk) {
            const int kc = kk * 16;
            uint32_t bh[4][2];
#pragma unroll
            for (int p = 0; p < 2; ++p) {
                const uint32_t boff =
                    ((uint32_t)((wn * 32 + p * 16 + ((lane >> 4) << 3) + (lane & 7)) * ASTR
                                + kc + (((lane >> 3) & 1) << 3))) << 1;
                uint32_t r0, r1, r2, r3;
                ldsm4(r0, r1, r2, r3, bb + PANELB + boff);
                bh[p * 2][0] = r0; bh[p * 2][1] = r1; bh[p * 2 + 1][0] = r2; bh[p * 2 + 1][1] = r3;
            }
#pragma unroll
            for (int mt = 0; mt < 4; ++mt) {
                const uint32_t aoff =
                    ((uint32_t)((wm * 64 + mt * 16 + (lane & 15)) * ASTR + kc + ((lane >> 4) << 3))) << 1;
                uint32_t ah[4];
                ldsm4(ah[0], ah[1], ah[2], ah[3], bb + aoff);
#pragma unroll
                for (int nt = 0; nt < 4; ++nt)
                    mma16816(acc[mt][nt], ah, bh[nt]);
            }
        }
    };

    const int steps = K >> 5;
    if (AMODE == 3) cpaA(0, 0); else loadA(0);
    cpaB(0, 0);
    CP_COMMIT();
    if (AMODE != 3) stsA(0);
    CP_WAIT0();
    __syncthreads();

    for (int s = 0; s < steps; ++s) {
        const int buf = s & 1, nbuf = buf ^ 1;
        const bool more = (s + 1 < steps);
        if (more) {
            if (AMODE == 3) cpaA(s + 1, nbuf); else loadA(s + 1);
            cpaB(s + 1, nbuf);
            CP_COMMIT();
        }
        domma(buf);
        if (more) {
            if (AMODE != 3) stsA(nbuf);
            CP_WAIT0();
            __syncthreads();
        }
    }

    // ---- epilogue ----
    const int r0base = m0 + wm * 64 + (lane >> 2);
    const int cbase  = n0 + wn * 32 + (lane & 3) * 2;
#pragma unroll
    for (int mt = 0; mt < 4; ++mt) {
#pragma unroll
        for (int nt = 0; nt < 4; ++nt) {
            const int cB = cbase + nt * 8;
            const float b0v = bsel[cB], b1v = bsel[cB + 1];
            float c0 = acc[mt][nt][0] + b0v, c1 = acc[mt][nt][1] + b1v;
            float c2 = acc[mt][nt][2] + b0v, c3 = acc[mt][nt][3] + b1v;
            if (RELU) {
                c0 = fmaxf(c0, 0.f); c1 = fmaxf(c1, 0.f);
                c2 = fmaxf(c2, 0.f); c3 = fmaxf(c3, 0.f);
            }
            const int gR0 = r0base + mt * 16, gR1 = gR0 + 8;
            if (OUTSPLIT == 0) {
                if (gR0 < M) *(float2*)(Cf + (size_t)gR0 * ldc + cB) = make_float2(c0, c1);
                if (gR1 < M) *(float2*)(Cf + (size_t)gR1 * ldc + cB) = make_float2(c2, c3);
            } else {
                if (gR0 < M) *(uint32_t*)(Csel + (size_t)gR0 * ldc + cB) = pack_h2(c0, c1);
                if (gR1 < M) *(uint32_t*)(Csel + (size_t)gR1 * ldc + cB) = pack_h2(c2, c3);
            }
        }
    }
}

// ---------------- fused weight prep ----------------
#define S_W1 262144
#define S_W2 131072
#define S_G  49152
#define S_R1 131072
#define S_R2 524288
#define S_TOTAL (S_W1 + S_W2 + 4*S_G + S_R1 + S_R2)

__global__ void cvt_all_kernel(const float* __restrict__ W1, const float* __restrict__ W2,
                               const float* __restrict__ GiW, const float* __restrict__ GiU,
                               const float* __restrict__ GtW, const float* __restrict__ GtU,
                               const float* __restrict__ R1, const float* __restrict__ R2)
{
    int i = blockIdx.x * blockDim.x + threadIdx.x;
    if (i >= S_TOTAL) return;
    if (i < S_W1) {
        int k = i / 1024, n = i % 1024;
        g_W1t[(size_t)n * 256 + k] = __float2half_rn(W1[i]);
        return;
    }
    i -= S_W1;
    if (i < S_W2) {
        int k = i / 128, n = i % 128;
        g_W2t[(size_t)n * 1024 + k] = __float2half_rn(W2[i]);
        return;
    }
    i -= S_W2;
    if (i < 4 * S_G) {
        int seg = i / S_G, j = i % S_G;
        int k = j / 384, n = j % 384;
        const float* src = (seg == 0) ? GiW : (seg == 1) ? GiU : (seg == 2) ? GtW : GtU;
        __half* dst = (seg == 0) ? g_GiW : (seg == 1) ? g_GiU : (seg == 2) ? g_GtW : g_GtU;
        dst[(size_t)n * 128 + k] = __float2half_rn(src[j]);
        return;
    }
    i -= 4 * S_G;
    if (i < S_R1) {
        int k = i / 1024, n = i % 1024;
        g_R1t[(size_t)n * 128 + k] = __float2half_rn(R1[i]);
        return;
    }
    i -= S_R1;
    {
        int k = i / 512, n = i % 512;
        g_R2t[(size_t)n * 1024 + k] = __float2half_rn(R2[i]);
    }
}

// ---------------- glue ----------------
__global__ void init_h_kernel(const int* __restrict__ nodes, const float* __restrict__ embed)
{
    int i = blockIdx.x * blockDim.x + threadIdx.x;
    if (i >= N_TOTAL * D) return;
    int row = i >> 7, c = i & 127;
    float v = embed[nodes[row / WINDOW] * D + c];
    g_h[i] = v;
    g_h16[i] = __float2half_rn(v);
}
__global__ void zero_cnt_kernel()
{
    int i = blockIdx.x * blockDim.x + threadIdx.x;
    if (i < N_TOTAL) g_cnt[i] = 0;
}
__global__ void count_ie_kernel(const int* __restrict__ ie)
{
    int e = blockIdx.x * blockDim.x + threadIdx.x;
    if (e >= NE) return;
    int tt = ie[e * 3 + 0] % WINDOW, d2 = ie[e * 3 + 2];
    atomicAdd(&g_cnt[tt * N_NODES + d2], 1);
}
__global__ void scan_kernel()
{
    __shared__ int ssum[1024];
    const int tid = threadIdx.x;
    const int CH = (N_TOTAL + 1023) / 1024;
    const int base = tid * CH;
    int s = 0;
    for (int i = 0; i < CH; ++i) {
        int idx = base + i;
        if (idx < N_TOTAL) s += g_cnt[idx];
    }
    ssum[tid] = s;
    __syncthreads();
    for (int off = 1; off < 1024; off <<= 1) {
        int v = (tid >= off) ? ssum[tid - off] : 0;
        __syncthreads();
        ssum[tid] += v;
        __syncthreads();
    }
    int run = ssum[tid] - s;
    for (int i = 0; i < CH; ++i) {
        int idx = base + i;
        if (idx < N_TOTAL) {
            g_csr[idx] = run;
            g_cur[idx] = run;
            run += g_cnt[idx];
        }
    }
    if (tid == 1023) g_csr[N_TOTAL] = run;
}
__global__ void place_kernel(const int* __restrict__ ie)
{
    int e = blockIdx.x * blockDim.x + threadIdx.x;
    if (e >= NE) return;
    int tt = ie[e * 3 + 0] % WINDOW, s = ie[e * 3 + 1], d2 = ie[e * 3 + 2];
    int dst = tt * N_NODES + d2;
    int pos = atomicAdd(&g_cur[dst], 1);
    g_nidx[pos] = tt * N_NODES + s;
    g_midx[pos] = dst;
}
__device__ __forceinline__ float sigmoidf(float x) { return 1.f / (1.f + expf(-x)); }
__global__ void gru_kernel()
{
    int i = blockIdx.x * blockDim.x + threadIdx.x;
    if (i >= N_TOTAL * 64) return;
    int r = i >> 6, c2 = i & 63;
    const __half2* xg = (const __half2*)(g_xg16 + (size_t)r * 384);
    const __half2* hg = (const __half2*)(g_hg16 + (size_t)r * 384);
    float2 xz = __half22float2(xg[c2]),       hz = __half22float2(hg[c2]);
    float2 xr = __half22float2(xg[64 + c2]),  hr = __half22float2(hg[64 + c2]);
    float2 xh = __half22float2(xg[128 + c2]), hh = __half22float2(hg[128 + c2]);
    float2 h = *(float2*)(g_h + (size_t)r * 128 + c2 * 2);
    float z0 = sigmoidf(xz.x + hz.x), z1 = sigmoidf(xz.y + hz.y);
    float r0 = sigmoidf(xr.x + hr.x), r1 = sigmoidf(xr.y + hr.y);
    float hc0 = tanhf(xh.x + r0 * hh.x), hc1 = tanhf(xh.y + r1 * hh.y);
    float2 o;
    o.x = z0 * h.x + (1.f - z0) * hc0;
    o.y = z1 * h.y + (1.f - z1) * hc1;
    *(float2*)(g_h + (size_t)r * 128 + c2 * 2) = o;
    *(uint32_t*)(g_h16 + (size_t)r * 128 + c2 * 2) = pack_h2(o.x, o.y);
}
__global__ void logits_softmax_kernel(const float* __restrict__ W3,
                                      const float* __restrict__ b3,
                                      float* __restrict__ out)
{
    const int row = blockIdx.x;
    const int w = threadIdx.x >> 5, lane = threadIdx.x & 31;
    __shared__ float lg[10];
    float s = 0.f;
    for (int k = lane; k < 512; k += 32)
        s += g_x2[(size_t)row * 512 + k] * W3[k * 10 + w];
#pragma unroll
    for (int o = 16; o; o >>= 1) s += __shfl_down_sync(0xffffffff, s, o);
    if (lane == 0) lg[w] = s + b3[w];
    __syncthreads();
    if (threadIdx.x == 0) {
        float mx = lg[0];
#pragma unroll
        for (int c = 1; c < 10; ++c) mx = fmaxf(mx, lg[c]);
        float e[10], sum = 0.f;
#pragma unroll
        for (int c = 0; c < 10; ++c) { e[c] = expf(lg[c] - mx); sum += e[c]; }
#pragma unroll
        for (int c = 0; c < 10; ++c) out[row * 10 + c] = e[c] / sum;
    }
}

// ---------------- host ----------------
extern "C" void kernel_launch(void* const* d_in, const int* in_sizes, int n_in,
                              void* d_out, int out_size)
{
    const int*   ie        = (const int*)  d_in[0];
    const int*   nodes     = (const int*)  d_in[1];
    const float* embed     = (const float*)d_in[2];
    const float* msg_W1    = (const float*)d_in[3];
    const float* msg_b1    = (const float*)d_in[4];
    const float* msg_W2    = (const float*)d_in[5];
    const float* msg_b2    = (const float*)d_in[6];
    const float* gru_int_W = (const float*)d_in[7];
    const float* gru_int_U = (const float*)d_in[8];
    const float* gru_int_b = (const float*)d_in[9];
    const float* gru_tmp_W = (const float*)d_in[10];
    const float* gru_tmp_U = (const float*)d_in[11];
    const float* gru_tmp_b = (const float*)d_in[12];
    const float* ro_W1     = (const float*)d_in[13];
    const float* ro_b1     = (const float*)d_in[14];
    const float* ro_W2     = (const float*)d_in[15];
    const float* ro_b2     = (const float*)d_in[16];
    const float* ro_W3     = (const float*)d_in[17];
    const float* ro_b3     = (const float*)d_in[18];
    float* out = (float*)d_out;

    float *h_p, *x2_p, *zero_p;
    int *nidx_p, *midx_p, *csr_p;
    __half *h16_p, *P_p, *Q_p, *m_p, *xg_p, *hg_p, *hid_p;
    __half *w1, *w2, *gi, *gu, *gt, *gv, *r1, *r2;
    cudaGetSymbolAddress((void**)&h_p, g_h);
    cudaGetSymbolAddress((void**)&h16_p, g_h16);
    cudaGetSymbolAddress((void**)&x2_p, g_x2);
    cudaGetSymbolAddress((void**)&zero_p, g_zero1024);
    cudaGetSymbolAddress((void**)&nidx_p, g_nidx);
    cudaGetSymbolAddress((void**)&midx_p, g_midx);
    cudaGetSymbolAddress((void**)&csr_p, g_csr);
    cudaGetSymbolAddress((void**)&P_p, g_P16);
    cudaGetSymbolAddress((void**)&Q_p, g_Q16);
    cudaGetSymbolAddress((void**)&m_p, g_m16);
    cudaGetSymbolAddress((void**)&xg_p, g_xg16);
    cudaGetSymbolAddress((void**)&hg_p, g_hg16);
    cudaGetSymbolAddress((void**)&hid_p, g_hid);
    cudaGetSymbolAddress((void**)&w1, g_W1t);
    cudaGetSymbolAddress((void**)&w2, g_W2t);
    cudaGetSymbolAddress((void**)&gi, g_GiW);
    cudaGetSymbolAddress((void**)&gu, g_GiU);
    cudaGetSymbolAddress((void**)&gt, g_GtW);
    cudaGetSymbolAddress((void**)&gv, g_GtU);
    cudaGetSymbolAddress((void**)&r1, g_R1t);
    cudaGetSymbolAddress((void**)&r2, g_R2t);

    cudaFuncSetAttribute(hmma_gemm<3,0,1>,  cudaFuncAttributeMaxDynamicSharedMemorySize, SMEM_BYTES);
    cudaFuncSetAttribute(hmma_gemm<3,1,1>,  cudaFuncAttributeMaxDynamicSharedMemorySize, SMEM_BYTES);
    cudaFuncSetAttribute(hmma_gemm<4,1,1>,  cudaFuncAttributeMaxDynamicSharedMemorySize, SMEM_BYTES);
    cudaFuncSetAttribute(hmma_gemm<5,1,1>,  cudaFuncAttributeMaxDynamicSharedMemorySize, SMEM_BYTES);
    cudaFuncSetAttribute(hmma_gemm<8,1,0>,  cudaFuncAttributeMaxDynamicSharedMemorySize, SMEM_BYTES);
    cudaFuncSetAttribute(hmma_gemm<9,1,0>,  cudaFuncAttributeMaxDynamicSharedMemorySize, SMEM_BYTES);
    cudaFuncSetAttribute(hmma_gemm<12,1,0>, cudaFuncAttributeMaxDynamicSharedMemorySize, SMEM_BYTES);

    const int EL = 256;
    cvt_all_kernel<<<(S_TOTAL + EL-1)/EL, EL>>>(msg_W1, msg_W2, gru_int_W, gru_int_U,
                                                gru_tmp_W, gru_tmp_U, ro_W1, ro_W2);
    init_h_kernel<<<(N_TOTAL*D + EL-1)/EL, EL>>>(nodes, embed);
    zero_cnt_kernel<<<(N_TOTAL + EL-1)/EL, EL>>>();
    count_ie_kernel<<<(NE + EL-1)/EL, EL>>>(ie);
    scan_kernel<<<1, 1024>>>();
    place_kernel<<<(NE + EL-1)/EL, EL>>>(ie);

    const int MT_E = NE / 128;
    const int MT_T = (TE2 + 127) / 128;
    const int MT_N = (N_TOTAL + 127) / 128;
    const int MT_R = (N_NODES + 127) / 128;

    for (int it = 0; it < 2; ++it) {
        // ---- interaction stage ----
        hmma_gemm<12,1,0><<<dim3(8, MT_N, 2), 256, SMEM_BYTES>>>(
            nullptr, h16_p, nullptr, nullptr, D, nullptr, nullptr, nullptr,
            w1, w1 + 128, 256, msg_b1, zero_p, nullptr, P_p, Q_p, HID, N_TOTAL, D);
        hmma_gemm<4,1,1><<<dim3(1, MT_E), 256, SMEM_BYTES>>>(
            nullptr, P_p, Q_p, nullptr, 0, nidx_p, midx_p, nullptr,
            w2, nullptr, HID, msg_b2, nullptr, nullptr, m_p, nullptr, D, NE, HID);
        hmma_gemm<8,1,0><<<dim3(3, MT_N, 2), 256, SMEM_BYTES>>>(
            nullptr, h16_p, nullptr, m_p, D, nullptr, nullptr, csr_p,
            gi, gu, D, gru_int_b, gru_int_b + 384, nullptr, xg_p, hg_p, 384, N_TOTAL, D);
        gru_kernel<<<(N_TOTAL*64 + EL-1)/EL, EL>>>();

        // ---- temporal stage ----
        hmma_gemm<12,1,0><<<dim3(8, MT_N, 2), 256, SMEM_BYTES>>>(
            nullptr, h16_p, nullptr, nullptr, D, nullptr, nullptr, nullptr,
            w1, w1 + 128, 256, msg_b1, zero_p, nullptr, P_p, Q_p, HID, N_TOTAL, D);
        hmma_gemm<5,1,1><<<dim3(1, MT_T), 256, SMEM_BYTES>>>(
            nullptr, P_p, Q_p, nullptr, 0, nullptr, nullptr, nullptr,
            w2, nullptr, HID, msg_b2, nullptr, nullptr, m_p, nullptr, D, TE2, HID);
        hmma_gemm<9,1,0><<<dim3(3, MT_N, 2), 256, SMEM_BYTES>>>(
            nullptr, h16_p, nullptr, m_p, D, nullptr, nullptr, nullptr,
            gt, gv, D, gru_tmp_b, gru_tmp_b + 384, nullptr, xg_p, hg_p, 384, N_TOTAL, D);
        gru_kernel<<<(N_TOTAL*64 + EL-1)/EL, EL>>>();
    }

    // ---- readout (h via fp16 mirror, cp.async path) ----
    hmma_gemm<3,1,1><<<dim3(8, MT_R), 256, SMEM_BYTES>>>(
        nullptr, nullptr, nullptr, h16_p, D, nullptr, nullptr, nullptr,
        r1, nullptr, D, ro_b1, nullptr, nullptr, hid_p, nullptr, HID, N_NODES, D);
    hmma_gemm<3,0,1><<<dim3(4, MT_R), 256, SMEM_BYTES>>>(
        nullptr, nullptr, nullptr, hid_p, HID, nullptr, nullptr, nullptr,
        r2, nullptr, HID, ro_b2, nullptr, x2_p, nullptr, nullptr, 512, N_NODES, HID);
    logits_softmax_kernel<<<N_NODES, 320>>>(ro_W3, ro_b3, out);
}

// round 17
// speedup vs baseline: 1.1115x; 1.0056x over previous
#include <cuda_runtime.h>
#include <cuda_fp16.h>
#include <math.h>
#include <stdint.h>

#define D        128
#define N_NODES  5000
#define WINDOW   10
#define N_TOTAL  50000
#define NE       131072
#define HID      1024
#define TEDGE    45000
#define TE2      90000

// ---------------- device scratch ----------------
__device__ __align__(16) __half g_h16[N_TOTAL * D];   // fp16-resident node state
__device__ int   g_cnt[N_TOTAL];
__device__ int   g_csr[N_TOTAL + 1];
__device__ int   g_cur[N_TOTAL];
__device__ int   g_nidx[NE];
__device__ int   g_midx[NE];
__device__ __align__(16) float g_x2[N_NODES * 512];
__device__ __align__(16) float g_zero1024[1024];

// fp16 intermediates
__device__ __align__(16) __half g_P16[(size_t)N_TOTAL * HID];
__device__ __align__(16) __half g_Q16[(size_t)N_TOTAL * HID];
__device__ __align__(16) __half g_m16[(size_t)NE * D];
__device__ __align__(16) __half g_xg16[(size_t)N_TOTAL * 384];
__device__ __align__(16) __half g_hg16[(size_t)N_TOTAL * 384];
__device__ __align__(16) __half g_hid[(size_t)N_NODES * HID];

// transposed fp16 weights, layout [N][K]
__device__ __align__(16) __half g_W1t[HID * 256];
__device__ __align__(16) __half g_W2t[D * HID];
__device__ __align__(16) __half g_GiW[384 * D];
__device__ __align__(16) __half g_GiU[384 * D];
__device__ __align__(16) __half g_GtW[384 * D];
__device__ __align__(16) __half g_GtU[384 * D];
__device__ __align__(16) __half g_R1t[HID * D];
__device__ __align__(16) __half g_R2t[512 * HID];

// ---------------- helpers ----------------
__device__ __forceinline__ uint32_t smem_u32(const void* p) {
    uint32_t a;
    asm("{ .reg .u64 t; cvta.to.shared.u64 t, %1; cvt.u32.u64 %0, t; }" : "=r"(a) : "l"(p));
    return a;
}
__device__ __forceinline__ void ldsm4(uint32_t& r0, uint32_t& r1, uint32_t& r2, uint32_t& r3, uint32_t addr) {
    asm volatile("ldmatrix.sync.aligned.m8n8.x4.shared.b16 {%0,%1,%2,%3}, [%4];"
                 : "=r"(r0), "=r"(r1), "=r"(r2), "=r"(r3) : "r"(addr));
}
__device__ __forceinline__ void mma16816(float* c, const uint32_t* a, const uint32_t* b) {
    asm volatile("mma.sync.aligned.m16n8k16.row.col.f32.f16.f16.f32 "
                 "{%0,%1,%2,%3}, {%4,%5,%6,%7}, {%8,%9}, {%0,%1,%2,%3};"
                 : "+f"(c[0]), "+f"(c[1]), "+f"(c[2]), "+f"(c[3])
                 : "r"(a[0]), "r"(a[1]), "r"(a[2]), "r"(a[3]), "r"(b[0]), "r"(b[1]));
}
__device__ __forceinline__ void cp16(uint32_t saddr, const void* g) {
    asm volatile("cp.async.cg.shared.global [%0], [%1], 16;" :: "r"(saddr), "l"(g));
}
#define CP_COMMIT() asm volatile("cp.async.commit_group;" ::: "memory")
#define CP_WAIT0()  asm volatile("cp.async.wait_group 0;" ::: "memory")

__device__ __forceinline__ uint32_t pack_h2(float x, float y) {
    __half2 h = __floats2half2_rn(x, y);
    return *(uint32_t*)&h;
}
__device__ __forceinline__ uint32_t hadd2_relu(uint32_t a, uint32_t b) {
    __half2 s = __hadd2(*(__half2*)&a, *(__half2*)&b);
    __half2 z = __float2half2_rn(0.f);
    __half2 r = __hmax2(s, z);
    return *(uint32_t*)&r;
}
__device__ __forceinline__ uint32_t havg2(uint32_t a, uint32_t b) {
    __half2 s = __hadd2(*(__half2*)&a, *(__half2*)&b);
    __half2 hlf = __float2half2_rn(0.5f);
    __half2 r = __hmul2(s, hlf);
    return *(uint32_t*)&r;
}

// ---------------- fp16 HMMA GEMM, double-buffered, 2 CTAs/SM ----------------
// AMODE 0:  A fp32 row-major stride lda
// AMODE 3:  A fp16 row-major stride lda (cp.async)
// AMODE 4:  A[r,k] = relu(P16[nidx[r]][k] + Q16[midx[r]][k])      (bases hoisted)
// AMODE 5:  same with analytic temporal indices                   (bases hoisted)
// AMODE 8:  dual interaction-GRU: z=0 CSR-mean(m16 via Ah_g); z=1 fp16 h via Ph
// AMODE 9:  dual temporal-GRU:    z=0 temporal-mean(m16);     z=1 fp16 h via Ph
// AMODE 12: dual P|Q: fp16 h loader via Ph, both z; z selects B/bias/output
#define ASTR   56
#define PANEL  (128 * ASTR)
#define PANELB (PANEL * 2)               // 14336 B
#define BUF_BYTES (2 * PANELB)           // 28672 (A, B)
#define SMEM_BYTES (2 * BUF_BYTES)       // 57344

template<int AMODE, int OUTSPLIT, int RELU>
__global__ __launch_bounds__(256, 2)
void hmma_gemm(const float* __restrict__ Af,
               const __half* __restrict__ Ph,
               const __half* __restrict__ Qh,
               const __half* __restrict__ Ah_g,
               int lda,
               const int* __restrict__ idxA, const int* __restrict__ idxB,
               const int* __restrict__ csr,
               const __half* __restrict__ Bw,
               const __half* __restrict__ Bw2,
               int ldb,
               const float* __restrict__ bias,
               const float* __restrict__ bias2,
               float* __restrict__ Cf,
               __half* __restrict__ Chi,
               __half* __restrict__ Chi2,
               int ldc, int M, int K)
{
    extern __shared__ __half smbuf[];
    const uint32_t sbase = smem_u32(smbuf);

    const int t = threadIdx.x, lane = t & 31, w = t >> 5;
    const int wm = w >> 2, wn = w & 3;
    const int m0 = blockIdx.y * 128, n0 = blockIdx.x * 128;
    const bool DUAL = (AMODE == 8 || AMODE == 9 || AMODE == 12);
    const int z1 = DUAL ? (int)blockIdx.z : 0;
    const int lrow = t >> 1, lhalf = t & 1;
    const uint32_t arow_off = ((uint32_t)(lrow * ASTR + lhalf * 16)) << 1;

    const __half* Bsel = z1 ? Bw2 : Bw;
    const float*  bsel = z1 ? bias2 : bias;
    __half*       Csel = z1 ? Chi2 : Chi;

    // hoisted loader state
    const __half *gP = nullptr, *gQ = nullptr;       // AMODE 4/5
    const __half *tA = nullptr, *tB = nullptr;       // AMODE 9 z=0
    int segBeg = 0, segEnd = 0;                      // AMODE 8 z=0
    {
        int gRow = m0 + lrow; if (gRow >= M) gRow = M - 1;
        if (AMODE == 4 || AMODE == 5) {
            int n_, m_;
            if (AMODE == 4) { n_ = idxA[gRow]; m_ = idxB[gRow]; }
            else {
                if (gRow < TEDGE) { n_ = gRow;                   m_ = gRow + N_NODES; }
                else              { n_ = gRow - TEDGE + N_NODES; m_ = gRow - TEDGE;   }
            }
            gP = Ph + (size_t)n_ * HID;
            gQ = Qh + (size_t)m_ * HID;
        } else if (AMODE == 8 && z1 == 0) {
            segBeg = csr[gRow]; segEnd = csr[gRow + 1];
        } else if (AMODE == 9 && z1 == 0) {
            const int v = gRow;
            if (v >= N_NODES) tA = Ah_g + (size_t)(v - N_NODES) * D;
            if (v < TEDGE)    tB = Ah_g + (size_t)(TEDGE + v) * D;
        }
    }

    float acc[4][4][4];
#pragma unroll
    for (int i = 0; i < 4; ++i)
#pragma unroll
        for (int j = 0; j < 4; ++j)
#pragma unroll
            for (int q = 0; q < 4; ++q) acc[i][j][q] = 0.f;

    uint32_t rh[8];

    auto loadH16 = [&](const __half* src) {
        uint4 a0 = ((const uint4*)src)[0];
        uint4 a1 = ((const uint4*)src)[1];
        rh[0] = a0.x; rh[1] = a0.y; rh[2] = a0.z; rh[3] = a0.w;
        rh[4] = a1.x; rh[5] = a1.y; rh[6] = a1.z; rh[7] = a1.w;
    };

    auto loadA = [&](int s) {
        if (AMODE == 3) return;
        const int k0 = s << 5;
        int gRow = m0 + lrow; if (gRow >= M) gRow = M - 1;
        const int koff = k0 + lhalf * 16;
        if (AMODE == 4 || AMODE == 5) {
            const uint4* p = (const uint4*)(gP + koff);
            const uint4* q = (const uint4*)(gQ + koff);
            uint4 p0 = p[0], p1 = p[1], q0 = q[0], q1 = q[1];
            rh[0] = hadd2_relu(p0.x, q0.x); rh[1] = hadd2_relu(p0.y, q0.y);
            rh[2] = hadd2_relu(p0.z, q0.z); rh[3] = hadd2_relu(p0.w, q0.w);
            rh[4] = hadd2_relu(p1.x, q1.x); rh[5] = hadd2_relu(p1.y, q1.y);
            rh[6] = hadd2_relu(p1.z, q1.z); rh[7] = hadd2_relu(p1.w, q1.w);
        } else if (AMODE == 9 && z1 == 0) {
            uint4 a0 = make_uint4(0,0,0,0), a1 = a0, b0 = a0, b1 = a0;
            if (tA) { const uint4* r = (const uint4*)(tA + koff); a0 = r[0]; a1 = r[1]; }
            if (tB) { const uint4* r = (const uint4*)(tB + koff); b0 = r[0]; b1 = r[1]; }
            if (tA && tB) {
                rh[0] = havg2(a0.x, b0.x); rh[1] = havg2(a0.y, b0.y);
                rh[2] = havg2(a0.z, b0.z); rh[3] = havg2(a0.w, b0.w);
                rh[4] = havg2(a1.x, b1.x); rh[5] = havg2(a1.y, b1.y);
                rh[6] = havg2(a1.z, b1.z); rh[7] = havg2(a1.w, b1.w);
            } else if (tA) {
                rh[0] = a0.x; rh[1] = a0.y; rh[2] = a0.z; rh[3] = a0.w;
                rh[4] = a1.x; rh[5] = a1.y; rh[6] = a1.z; rh[7] = a1.w;
            } else {
                rh[0] = b0.x; rh[1] = b0.y; rh[2] = b0.z; rh[3] = b0.w;
                rh[4] = b1.x; rh[5] = b1.y; rh[6] = b1.z; rh[7] = b1.w;
            }
        } else if (AMODE == 8 && z1 == 0) {
            float sx[16];
#pragma unroll
            for (int i = 0; i < 16; ++i) sx[i] = 0.f;
            for (int j = segBeg; j < segEnd; ++j) {
                const uint4* r = (const uint4*)(Ah_g + (size_t)j * D + koff);
                uint4 v0 = r[0], v1 = r[1];
                uint32_t ww[8] = {v0.x, v0.y, v0.z, v0.w, v1.x, v1.y, v1.z, v1.w};
#pragma unroll
                for (int i = 0; i < 8; ++i) {
                    float2 f = __half22float2(*(__half2*)&ww[i]);
                    sx[2*i]     += f.x;
                    sx[2*i + 1] += f.y;
                }
            }
            const float scale = (segEnd > segBeg) ? 1.f / (float)(segEnd - segBeg) : 0.f;
#pragma unroll
            for (int i = 0; i < 8; ++i)
                rh[i] = pack_h2(sx[2*i] * scale, sx[2*i+1] * scale);
        } else if (AMODE == 12 || ((AMODE == 8 || AMODE == 9) && z1 == 1)) {
            loadH16(Ph + (size_t)gRow * D + koff);
        } else {   // AMODE 0: fp32 source Af
            const float* src = Af + (size_t)gRow * lda + koff;
            float vv[16];
#pragma unroll
            for (int i = 0; i < 16; i += 4) {
                float4 v = *(const float4*)(src + i);
                vv[i] = v.x; vv[i+1] = v.y; vv[i+2] = v.z; vv[i+3] = v.w;
            }
#pragma unroll
            for (int i = 0; i < 8; ++i) rh[i] = pack_h2(vv[2*i], vv[2*i+1]);
        }
    };
    auto stsA = [&](int buf) {
        if (AMODE == 3) return;
        __half* dh = smbuf + (size_t)buf * (BUF_BYTES / 2) + lrow * ASTR + lhalf * 16;
        *(uint4*)dh       = make_uint4(rh[0], rh[1], rh[2], rh[3]);
        *(uint4*)(dh + 8) = make_uint4(rh[4], rh[5], rh[6], rh[7]);
    };
    auto cpaA = [&](int s, int buf) {   // AMODE 3
        const int k0 = s << 5;
        int gRow = m0 + lrow; if (gRow >= M) gRow = M - 1;
        const size_t off = (size_t)gRow * lda + k0 + lhalf * 16;
        const uint32_t d = sbase + buf * BUF_BYTES + arow_off;
        cp16(d,      Ah_g + off);
        cp16(d + 16, Ah_g + off + 8);
    };
    auto cpaB = [&](int s, int buf) {
        const int k0 = s << 5;
        const size_t off = (size_t)(n0 + lrow) * ldb + k0 + lhalf * 16;
        const uint32_t d = sbase + buf * BUF_BYTES + PANELB + arow_off;
        cp16(d,      Bsel + off);
        cp16(d + 16, Bsel + off + 8);
    };
    auto domma = [&](int buf) {
        const uint32_t bb = sbase + buf * BUF_BYTES;
#pragma unroll
        for (int kk = 0; kk < 2; ++kk) {
            const int kc = kk * 16;
            uint32_t bh[4][2];
#pragma unroll
            for (int p = 0; p < 2; ++p) {
                const uint32_t boff =
                    ((uint32_t)((wn * 32 + p * 16 + ((lane >> 4) << 3) + (lane & 7)) * ASTR
                                + kc + (((lane >> 3) & 1) << 3))) << 1;
                uint32_t r0, r1, r2, r3;
                ldsm4(r0, r1, r2, r3, bb + PANELB + boff);
                bh[p * 2][0] = r0; bh[p * 2][1] = r1; bh[p * 2 + 1][0] = r2; bh[p * 2 + 1][1] = r3;
            }
#pragma unroll
            for (int mt = 0; mt < 4; ++mt) {
                const uint32_t aoff =
                    ((uint32_t)((wm * 64 + mt * 16 + (lane & 15)) * ASTR + kc + ((lane >> 4) << 3))) << 1;
                uint32_t ah[4];
                ldsm4(ah[0], ah[1], ah[2], ah[3], bb + aoff);
#pragma unroll
                for (int nt = 0; nt < 4; ++nt)
                    mma16816(acc[mt][nt], ah, bh[nt]);
            }
        }
    };

    const int steps = K >> 5;
    if (AMODE == 3) cpaA(0, 0); else loadA(0);
    cpaB(0, 0);
    CP_COMMIT();
    if (AMODE != 3) stsA(0);
    CP_WAIT0();
    __syncthreads();

    for (int s = 0; s < steps; ++s) {
        const int buf = s & 1, nbuf = buf ^ 1;
        const bool more = (s + 1 < steps);
        if (more) {
            if (AMODE == 3) cpaA(s + 1, nbuf); else loadA(s + 1);
            cpaB(s + 1, nbuf);
            CP_COMMIT();
        }
        domma(buf);
        if (more) {
            if (AMODE != 3) stsA(nbuf);
            CP_WAIT0();
            __syncthreads();
        }
    }

    // ---- epilogue ----
    const int r0base = m0 + wm * 64 + (lane >> 2);
    const int cbase  = n0 + wn * 32 + (lane & 3) * 2;
#pragma unroll
    for (int mt = 0; mt < 4; ++mt) {
#pragma unroll
        for (int nt = 0; nt < 4; ++nt) {
            const int cB = cbase + nt * 8;
            const float b0v = bsel[cB], b1v = bsel[cB + 1];
            float c0 = acc[mt][nt][0] + b0v, c1 = acc[mt][nt][1] + b1v;
            float c2 = acc[mt][nt][2] + b0v, c3 = acc[mt][nt][3] + b1v;
            if (RELU) {
                c0 = fmaxf(c0, 0.f); c1 = fmaxf(c1, 0.f);
                c2 = fmaxf(c2, 0.f); c3 = fmaxf(c3, 0.f);
            }
            const int gR0 = r0base + mt * 16, gR1 = gR0 + 8;
            if (OUTSPLIT == 0) {
                if (gR0 < M) *(float2*)(Cf + (size_t)gR0 * ldc + cB) = make_float2(c0, c1);
                if (gR1 < M) *(float2*)(Cf + (size_t)gR1 * ldc + cB) = make_float2(c2, c3);
            } else {
                if (gR0 < M) *(uint32_t*)(Csel + (size_t)gR0 * ldc + cB) = pack_h2(c0, c1);
                if (gR1 < M) *(uint32_t*)(Csel + (size_t)gR1 * ldc + cB) = pack_h2(c2, c3);
            }
        }
    }
}

// ---------------- fused weight prep ----------------
#define S_W1 262144
#define S_W2 131072
#define S_G  49152
#define S_R1 131072
#define S_R2 524288
#define S_TOTAL (S_W1 + S_W2 + 4*S_G + S_R1 + S_R2)

__global__ void cvt_all_kernel(const float* __restrict__ W1, const float* __restrict__ W2,
                               const float* __restrict__ GiW, const float* __restrict__ GiU,
                               const float* __restrict__ GtW, const float* __restrict__ GtU,
                               const float* __restrict__ R1, const float* __restrict__ R2)
{
    int i = blockIdx.x * blockDim.x + threadIdx.x;
    if (i >= S_TOTAL) return;
    if (i < S_W1) {
        int k = i / 1024, n = i % 1024;
        g_W1t[(size_t)n * 256 + k] = __float2half_rn(W1[i]);
        return;
    }
    i -= S_W1;
    if (i < S_W2) {
        int k = i / 128, n = i % 128;
        g_W2t[(size_t)n * 1024 + k] = __float2half_rn(W2[i]);
        return;
    }
    i -= S_W2;
    if (i < 4 * S_G) {
        int seg = i / S_G, j = i % S_G;
        int k = j / 384, n = j % 384;
        const float* src = (seg == 0) ? GiW : (seg == 1) ? GiU : (seg == 2) ? GtW : GtU;
        __half* dst = (seg == 0) ? g_GiW : (seg == 1) ? g_GiU : (seg == 2) ? g_GtW : g_GtU;
        dst[(size_t)n * 128 + k] = __float2half_rn(src[j]);
        return;
    }
    i -= 4 * S_G;
    if (i < S_R1) {
        int k = i / 1024, n = i % 1024;
        g_R1t[(size_t)n * 128 + k] = __float2half_rn(R1[i]);
        return;
    }
    i -= S_R1;
    {
        int k = i / 512, n = i % 512;
        g_R2t[(size_t)n * 1024 + k] = __float2half_rn(R2[i]);
    }
}

// ---------------- glue ----------------
__global__ void init_h_kernel(const int* __restrict__ nodes, const float* __restrict__ embed)
{
    int i = blockIdx.x * blockDim.x + threadIdx.x;
    if (i >= N_TOTAL * D) return;
    int row = i >> 7, c = i & 127;
    g_h16[i] = __float2half_rn(embed[nodes[row / WINDOW] * D + c]);
}
__global__ void zero_cnt_kernel()
{
    int i = blockIdx.x * blockDim.x + threadIdx.x;
    if (i < N_TOTAL) g_cnt[i] = 0;
}
__global__ void count_ie_kernel(const int* __restrict__ ie)
{
    int e = blockIdx.x * blockDim.x + threadIdx.x;
    if (e >= NE) return;
    int tt = ie[e * 3 + 0] % WINDOW, d2 = ie[e * 3 + 2];
    atomicAdd(&g_cnt[tt * N_NODES + d2], 1);
}
__global__ void scan_kernel()
{
    __shared__ int ssum[1024];
    const int tid = threadIdx.x;
    const int CH = (N_TOTAL + 1023) / 1024;
    const int base = tid * CH;
    int s = 0;
    for (int i = 0; i < CH; ++i) {
        int idx = base + i;
        if (idx < N_TOTAL) s += g_cnt[idx];
    }
    ssum[tid] = s;
    __syncthreads();
    for (int off = 1; off < 1024; off <<= 1) {
        int v = (tid >= off) ? ssum[tid - off] : 0;
        __syncthreads();
        ssum[tid] += v;
        __syncthreads();
    }
    int run = ssum[tid] - s;
    for (int i = 0; i < CH; ++i) {
        int idx = base + i;
        if (idx < N_TOTAL) {
            g_csr[idx] = run;
            g_cur[idx] = run;
            run += g_cnt[idx];
        }
    }
    if (tid == 1023) g_csr[N_TOTAL] = run;
}
__global__ void place_kernel(const int* __restrict__ ie)
{
    int e = blockIdx.x * blockDim.x + threadIdx.x;
    if (e >= NE) return;
    int tt = ie[e * 3 + 0] % WINDOW, s = ie[e * 3 + 1], d2 = ie[e * 3 + 2];
    int dst = tt * N_NODES + d2;
    int pos = atomicAdd(&g_cur[dst], 1);
    g_nidx[pos] = tt * N_NODES + s;
    g_midx[pos] = dst;
}
__device__ __forceinline__ float sigmoidf(float x) { return 1.f / (1.f + expf(-x)); }
__global__ void gru_kernel()
{
    int i = blockIdx.x * blockDim.x + threadIdx.x;
    if (i >= N_TOTAL * 64) return;
    int r = i >> 6, c2 = i & 63;
    const __half2* xg = (const __half2*)(g_xg16 + (size_t)r * 384);
    const __half2* hg = (const __half2*)(g_hg16 + (size_t)r * 384);
    float2 xz = __half22float2(xg[c2]),       hz = __half22float2(hg[c2]);
    float2 xr = __half22float2(xg[64 + c2]),  hr = __half22float2(hg[64 + c2]);
    float2 xh = __half22float2(xg[128 + c2]), hh = __half22float2(hg[128 + c2]);
    uint32_t hold = *(uint32_t*)(g_h16 + (size_t)r * 128 + c2 * 2);
    float2 h = __half22float2(*(__half2*)&hold);
    float z0 = sigmoidf(xz.x + hz.x), z1 = sigmoidf(xz.y + hz.y);
    float r0 = sigmoidf(xr.x + hr.x), r1 = sigmoidf(xr.y + hr.y);
    float hc0 = tanhf(xh.x + r0 * hh.x), hc1 = tanhf(xh.y + r1 * hh.y);
    float o0 = z0 * h.x + (1.f - z0) * hc0;
    float o1 = z1 * h.y + (1.f - z1) * hc1;
    *(uint32_t*)(g_h16 + (size_t)r * 128 + c2 * 2) = pack_h2(o0, o1);
}
__global__ void logits_softmax_kernel(const float* __restrict__ W3,
                                      const float* __restrict__ b3,
                                      float* __restrict__ out)
{
    const int row = blockIdx.x;
    const int w = threadIdx.x >> 5, lane = threadIdx.x & 31;
    __shared__ float lg[10];
    float s = 0.f;
    for (int k = lane; k < 512; k += 32)
        s += g_x2[(size_t)row * 512 + k] * W3[k * 10 + w];
#pragma unroll
    for (int o = 16; o; o >>= 1) s += __shfl_down_sync(0xffffffff, s, o);
    if (lane == 0) lg[w] = s + b3[w];
    __syncthreads();
    if (threadIdx.x == 0) {
        float mx = lg[0];
#pragma unroll
        for (int c = 1; c < 10; ++c) mx = fmaxf(mx, lg[c]);
        float e[10], sum = 0.f;
#pragma unroll
        for (int c = 0; c < 10; ++c) { e[c] = expf(lg[c] - mx); sum += e[c]; }
#pragma unroll
        for (int c = 0; c < 10; ++c) out[row * 10 + c] = e[c] / sum;
    }
}

// ---------------- host ----------------
extern "C" void kernel_launch(void* const* d_in, const int* in_sizes, int n_in,
                              void* d_out, int out_size)
{
    const int*   ie        = (const int*)  d_in[0];
    const int*   nodes     = (const int*)  d_in[1];
    const float* embed     = (const float*)d_in[2];
    const float* msg_W1    = (const float*)d_in[3];
    const float* msg_b1    = (const float*)d_in[4];
    const float* msg_W2    = (const float*)d_in[5];
    const float* msg_b2    = (const float*)d_in[6];
    const float* gru_int_W = (const float*)d_in[7];
    const float* gru_int_U = (const float*)d_in[8];
    const float* gru_int_b = (const float*)d_in[9];
    const float* gru_tmp_W = (const float*)d_in[10];
    const float* gru_tmp_U = (const float*)d_in[11];
    const float* gru_tmp_b = (const float*)d_in[12];
    const float* ro_W1     = (const float*)d_in[13];
    const float* ro_b1     = (const float*)d_in[14];
    const float* ro_W2     = (const float*)d_in[15];
    const float* ro_b2     = (const float*)d_in[16];
    const float* ro_W3     = (const float*)d_in[17];
    const float* ro_b3     = (const float*)d_in[18];
    float* out = (float*)d_out;

    float *x2_p, *zero_p;
    int *nidx_p, *midx_p, *csr_p;
    __half *h16_p, *P_p, *Q_p, *m_p, *xg_p, *hg_p, *hid_p;
    __half *w1, *w2, *gi, *gu, *gt, *gv, *r1, *r2;
    cudaGetSymbolAddress((void**)&h16_p, g_h16);
    cudaGetSymbolAddress((void**)&x2_p, g_x2);
    cudaGetSymbolAddress((void**)&zero_p, g_zero1024);
    cudaGetSymbolAddress((void**)&nidx_p, g_nidx);
    cudaGetSymbolAddress((void**)&midx_p, g_midx);
    cudaGetSymbolAddress((void**)&csr_p, g_csr);
    cudaGetSymbolAddress((void**)&P_p, g_P16);
    cudaGetSymbolAddress((void**)&Q_p, g_Q16);
    cudaGetSymbolAddress((void**)&m_p, g_m16);
    cudaGetSymbolAddress((void**)&xg_p, g_xg16);
    cudaGetSymbolAddress((void**)&hg_p, g_hg16);
    cudaGetSymbolAddress((void**)&hid_p, g_hid);
    cudaGetSymbolAddress((void**)&w1, g_W1t);
    cudaGetSymbolAddress((void**)&w2, g_W2t);
    cudaGetSymbolAddress((void**)&gi, g_GiW);
    cudaGetSymbolAddress((void**)&gu, g_GiU);
    cudaGetSymbolAddress((void**)&gt, g_GtW);
    cudaGetSymbolAddress((void**)&gv, g_GtU);
    cudaGetSymbolAddress((void**)&r1, g_R1t);
    cudaGetSymbolAddress((void**)&r2, g_R2t);

    cudaFuncSetAttribute(hmma_gemm<3,0,1>,  cudaFuncAttributeMaxDynamicSharedMemorySize, SMEM_BYTES);
    cudaFuncSetAttribute(hmma_gemm<3,1,1>,  cudaFuncAttributeMaxDynamicSharedMemorySize, SMEM_BYTES);
    cudaFuncSetAttribute(hmma_gemm<4,1,1>,  cudaFuncAttributeMaxDynamicSharedMemorySize, SMEM_BYTES);
    cudaFuncSetAttribute(hmma_gemm<5,1,1>,  cudaFuncAttributeMaxDynamicSharedMemorySize, SMEM_BYTES);
    cudaFuncSetAttribute(hmma_gemm<8,1,0>,  cudaFuncAttributeMaxDynamicSharedMemorySize, SMEM_BYTES);
    cudaFuncSetAttribute(hmma_gemm<9,1,0>,  cudaFuncAttributeMaxDynamicSharedMemorySize, SMEM_BYTES);
    cudaFuncSetAttribute(hmma_gemm<12,1,0>, cudaFuncAttributeMaxDynamicSharedMemorySize, SMEM_BYTES);

    const int EL = 256;
    cvt_all_kernel<<<(S_TOTAL + EL-1)/EL, EL>>>(msg_W1, msg_W2, gru_int_W, gru_int_U,
                                                gru_tmp_W, gru_tmp_U, ro_W1, ro_W2);
    init_h_kernel<<<(N_TOTAL*D + EL-1)/EL, EL>>>(nodes, embed);
    zero_cnt_kernel<<<(N_TOTAL + EL-1)/EL, EL>>>();
    count_ie_kernel<<<(NE + EL-1)/EL, EL>>>(ie);
    scan_kernel<<<1, 1024>>>();
    place_kernel<<<(NE + EL-1)/EL, EL>>>(ie);

    const int MT_E = NE / 128;
    const int MT_T = (TE2 + 127) / 128;
    const int MT_N = (N_TOTAL + 127) / 128;
    const int MT_R = (N_NODES + 127) / 128;

    for (int it = 0; it < 2; ++it) {
        // ---- interaction stage ----
        hmma_gemm<12,1,0><<<dim3(8, MT_N, 2), 256, SMEM_BYTES>>>(
            nullptr, h16_p, nullptr, nullptr, D, nullptr, nullptr, nullptr,
            w1, w1 + 128, 256, msg_b1, zero_p, nullptr, P_p, Q_p, HID, N_TOTAL, D);
        hmma_gemm<4,1,1><<<dim3(1, MT_E), 256, SMEM_BYTES>>>(
            nullptr, P_p, Q_p, nullptr, 0, nidx_p, midx_p, nullptr,
            w2, nullptr, HID, msg_b2, nullptr, nullptr, m_p, nullptr, D, NE, HID);
        hmma_gemm<8,1,0><<<dim3(3, MT_N, 2), 256, SMEM_BYTES>>>(
            nullptr, h16_p, nullptr, m_p, D, nullptr, nullptr, csr_p,
            gi, gu, D, gru_int_b, gru_int_b + 384, nullptr, xg_p, hg_p, 384, N_TOTAL, D);
        gru_kernel<<<(N_TOTAL*64 + EL-1)/EL, EL>>>();

        // ---- temporal stage ----
        hmma_gemm<12,1,0><<<dim3(8, MT_N, 2), 256, SMEM_BYTES>>>(
            nullptr, h16_p, nullptr, nullptr, D, nullptr, nullptr, nullptr,
            w1, w1 + 128, 256, msg_b1, zero_p, nullptr, P_p, Q_p, HID, N_TOTAL, D);
        hmma_gemm<5,1,1><<<dim3(1, MT_T), 256, SMEM_BYTES>>>(
            nullptr, P_p, Q_p, nullptr, 0, nullptr, nullptr, nullptr,
            w2, nullptr, HID, msg_b2, nullptr, nullptr, m_p, nullptr, D, TE2, HID);
        hmma_gemm<9,1,0><<<dim3(3, MT_N, 2), 256, SMEM_BYTES>>>(
            nullptr, h16_p, nullptr, m_p, D, nullptr, nullptr, nullptr,
            gt, gv, D, gru_tmp_b, gru_tmp_b + 384, nullptr, xg_p, hg_p, 384, N_TOTAL, D);
        gru_kernel<<<(N_TOTAL*64 + EL-1)/EL, EL>>>();
    }

    // ---- readout ----
    hmma_gemm<3,1,1><<<dim3(8, MT_R), 256, SMEM_BYTES>>>(
        nullptr, nullptr, nullptr, h16_p, D, nullptr, nullptr, nullptr,
        r1, nullptr, D, ro_b1, nullptr, nullptr, hid_p, nullptr, HID, N_NODES, D);
    hmma_gemm<3,0,1><<<dim3(4, MT_R), 256, SMEM_BYTES>>>(
        nullptr, nullptr, nullptr, hid_p, HID, nullptr, nullptr, nullptr,
        r2, nullptr, HID, ro_b2, nullptr, x2_p, nullptr, nullptr, 512, N_NODES, HID);
    logits_softmax_kernel<<<N_NODES, 320>>>(ro_W3, ro_b3, out);
}